// round 13
// baseline (speedup 1.0000x reference)
#include <cuda_runtime.h>

#define NT   128          // n*t
#define CH   256          // channels
#define HW   196          // h*w
#define ICN  64           // inter_channels
#define YW   224          // padded Y row width
#define OUTW 448
#define MASK_ELEMS (NT*2*OUTW*OUTW)

__device__ float g_Y[NT*ICN*YW];   // linear output (cols >=196 unused)
__device__ float g_m[NT*HW];
__device__ float g_v[NT*HW];
__device__ float g_Wt[CH*ICN];     // Wq transposed: [c][d]

typedef unsigned long long ull;

// ---- packed fp32x2 helpers ----
__device__ __forceinline__ ull pk2(float lo, float hi){
    ull r; asm("mov.b64 %0,{%1,%2};" : "=l"(r) : "f"(lo),"f"(hi)); return r;
}
__device__ __forceinline__ void upk2(ull v, float& lo, float& hi){
    asm("mov.b64 {%0,%1},%2;" : "=f"(lo),"=f"(hi) : "l"(v));
}
__device__ __forceinline__ ull fma2(ull a, ull b, ull c){
    ull d; asm("fma.rn.f32x2 %0,%1,%2,%3;" : "=l"(d) : "l"(a),"l"(b),"l"(c)); return d;
}

// ---------------------------------------------------------------------------
// Kernel 0: value linear v[n][i] = Wv.x[sn][:,i] - Wv[256]*lamv + bv, plus
// vtail output; blocks 0..15 also transpose Wq -> g_Wt (1024 elems each).
// ---------------------------------------------------------------------------
__global__ __launch_bounds__(196) void k_value(const float* __restrict__ x,
                                               const float* __restrict__ Wq,
                                               const float* __restrict__ Wv,
                                               const float* __restrict__ bv,
                                               const float* __restrict__ lam,
                                               const int*   __restrict__ index,
                                               float*       __restrict__ vtail)
{
    __shared__ float wv[257];
    const int n = blockIdx.x, tid = threadIdx.x;
    for (int i = tid; i < 257; i += 196) wv[i] = Wv[i];

    if (n < 16){
        const int base = n*1024;
        for (int j = tid; j < 1024; j += 196){
            int idx = base + j, c = idx >> 6, d = idx & 63;
            g_Wt[idx] = Wq[d*257 + c];
        }
    }
    __syncthreads();

    const int sn = index[n>>3]*8 + (n&7);
    const float* xb = x + (size_t)sn*CH*HW + tid;

    float a[8];
#pragma unroll
    for (int u=0;u<8;u++) a[u]=0.f;
#pragma unroll 4
    for (int c = 0; c < CH; c += 8){
#pragma unroll
        for (int u=0;u<8;u++)
            a[u] = fmaf(wv[c+u], xb[(size_t)(c+u)*HW], a[u]);
    }
    const float lamv = lam[0] - 0.5f;
    float v = ((a[0]+a[1])+(a[2]+a[3])) + ((a[4]+a[5])+(a[6]+a[7]))
              - wv[CH]*lamv + bv[0];
    g_v[n*HW + tid]  = v;
    vtail[n*HW + tid] = v;
}

// ---------------------------------------------------------------------------
// Kernel 1: Y[n][d][i] = sum_c Wq[d][c]*x[n][c][i].
// grid (2,128): blockIdx.x = d-half (32 rows), blockIdx.y = n.
// 224 threads: ty = d 16-subgroup, tx = column pair. Two alternating 4-deep
// prefetch banks used in place (no register copies).
// ---------------------------------------------------------------------------
__global__ __launch_bounds__(224, 3) void k_linear(const float* __restrict__ x)
{
    extern __shared__ float Ws[];                 // [256][32] this d-half
    const int dh = blockIdx.x, n = blockIdx.y;
    const int tid = threadIdx.x;
    const int ty = tid / 112, tx = tid % 112;
    const int txe = (tx < 98) ? tx : 97;

    {   // coalesced smem fill from pre-transposed weights
        float4* Ws4 = (float4*)Ws;
        const float4* Wt4 = (const float4*)g_Wt;
        for (int i4 = tid; i4 < 2048; i4 += 224){
            int c = i4 >> 3, dd4 = i4 & 7;
            Ws4[c*8 + dd4] = Wt4[c*16 + dh*8 + dd4];
        }
    }
    __syncthreads();

    const float2* xp = (const float2*)(x + (size_t)n*CH*HW) + txe;  // [c][txe]
    const float*  wp = Ws + ty*16;

    ull acc[2][8];
#pragma unroll
    for (int q=0;q<2;q++)
#pragma unroll
        for (int p=0;p<8;p++) acc[q][p]=0ull;

    float2 xa[4], xb_[4];
#pragma unroll
    for (int u=0;u<4;u++) xa[u]  = xp[(size_t)u*98];
#pragma unroll
    for (int u=0;u<4;u++) xb_[u] = xp[(size_t)(4+u)*98];

#define PROC_CH(XV, WOFF) do { \
        const ulonglong2* w = (const ulonglong2*)(wp + (WOFF)*32); \
        ulonglong2 w0 = w[0], w1 = w[1], w2 = w[2], w3 = w[3]; \
        ull x0 = pk2((XV).x,(XV).x), x1 = pk2((XV).y,(XV).y); \
        acc[0][0]=fma2(w0.x,x0,acc[0][0]); acc[1][0]=fma2(w0.x,x1,acc[1][0]); \
        acc[0][1]=fma2(w0.y,x0,acc[0][1]); acc[1][1]=fma2(w0.y,x1,acc[1][1]); \
        acc[0][2]=fma2(w1.x,x0,acc[0][2]); acc[1][2]=fma2(w1.x,x1,acc[1][2]); \
        acc[0][3]=fma2(w1.y,x0,acc[0][3]); acc[1][3]=fma2(w1.y,x1,acc[1][3]); \
        acc[0][4]=fma2(w2.x,x0,acc[0][4]); acc[1][4]=fma2(w2.x,x1,acc[1][4]); \
        acc[0][5]=fma2(w2.y,x0,acc[0][5]); acc[1][5]=fma2(w2.y,x1,acc[1][5]); \
        acc[0][6]=fma2(w3.x,x0,acc[0][6]); acc[1][6]=fma2(w3.x,x1,acc[1][6]); \
        acc[0][7]=fma2(w3.y,x0,acc[0][7]); acc[1][7]=fma2(w3.y,x1,acc[1][7]); \
    } while(0)

#pragma unroll 1
    for (int c = 0; c < CH; c += 8){
        // bank A: process channels c..c+3, refill with c+8..c+11 (valid c<CH-8)
        const float2* pfa = (c < CH-8) ? xp + 784  : xp;   // 8*98
#pragma unroll
        for (int u=0;u<4;u++){
            PROC_CH(xa[u], u);
            xa[u] = pfa[(size_t)u*98];
        }
        // bank B: process channels c+4..c+7, refill with c+12..c+15 (valid c<CH-8)
        const float2* pfb = (c < CH-8) ? xp + 1176 : xp;   // 12*98
#pragma unroll
        for (int u=0;u<4;u++){
            PROC_CH(xb_[u], 4+u);
            xb_[u] = pfb[(size_t)u*98];
        }
        xp += 784;
        wp += 256;            // 8 channels * 32 floats
    }
#undef PROC_CH

    if (tx < 98){
        float* yb = g_Y + (size_t)n*ICN*YW + (size_t)(dh*32 + ty*16)*YW + 2*tx;
#pragma unroll
        for (int p=0;p<8;p++){
            float a,b,cc,dd;
            upk2(acc[0][p], a, cc);
            upk2(acc[1][p], b, dd);
            *(float2*)&yb[(size_t)(2*p)*YW]   = make_float2(a, b);
            *(float2*)&yb[(size_t)(2*p+1)*YW] = make_float2(cc, dd);
        }
    }
}

// ---------------------------------------------------------------------------
// Kernel 2: attention + softmax + sigmoid -> g_m (value precomputed in g_v).
// One block/n, 512 threads (16 warps), FFMA2 score GEMM.
// ---------------------------------------------------------------------------
__global__ __launch_bounds__(512) void k_attn(const float* __restrict__ Wq,
                                              const float* __restrict__ bq,
                                              const float* __restrict__ lam,
                                              const int*   __restrict__ index)
{
    extern __shared__ float sm[];
    float* qs = sm;               // [64][224] pre-scaled q
    float* ks = sm + ICN*YW;      // [64][256] zero-padded k
    float* vs = ks + ICN*256;     // [256] zero-padded v
    __shared__ float qadd[64], kadd[64];

    const int n = blockIdx.x, tid = threadIdx.x;
    const float lamv = lam[0] - 0.5f;
    const int sn = index[n>>3]*8 + (n&7);

    if (tid < 64) {
        float tt = Wq[tid*257+256]*lamv, b = bq[tid];
        qadd[tid] = b+tt; kadd[tid] = b-tt;
    }
    if (tid < 256) vs[tid] = (tid < HW) ? g_v[n*HW + tid] : 0.f;
    __syncthreads();

    const float* Yq = g_Y + (size_t)n *ICN*YW;
    const float* Yk = g_Y + (size_t)sn*ICN*YW;
    for (int idx=tid; idx<ICN*YW; idx+=512){
        int d = idx/YW;
        qs[idx] = (Yq[idx] + qadd[d])*0.125f;     // fold 1/sqrt(64)
    }
    for (int idx=tid; idx<ICN*256; idx+=512){
        int d = idx>>8, j = idx&255;
        ks[idx] = (j<HW) ? (Yk[d*YW+j] + kadd[d]) : 0.f;
    }
    __syncthreads();

    const int warp = tid>>5, lane = tid&31;
    for (int it=0; it<2; it++){
        const int i0 = it*128 + warp*8;
        if (i0 >= HW) continue;                   // warp-uniform
        ull acc[8][4];
#pragma unroll
        for (int r=0;r<8;r++)
#pragma unroll
            for (int g=0;g<4;g++) acc[r][g]=0ull;

#pragma unroll 2
        for (int d=0; d<ICN; d++){
            ull kv[4];
#pragma unroll
            for (int g=0; g<4; g++)
                kv[g] = *(const ull*)&ks[d*256 + 2*lane + 64*g];
            float4 qa = *(const float4*)&qs[d*YW + i0];
            float4 qb = *(const float4*)&qs[d*YW + i0 + 4];
            float qv[8]={qa.x,qa.y,qa.z,qa.w,qb.x,qb.y,qb.z,qb.w};
#pragma unroll
            for (int r=0;r<8;r++){
                ull qd = pk2(qv[r],qv[r]);
#pragma unroll
                for (int g=0;g<4;g++) acc[r][g]=fma2(qd,kv[g],acc[r][g]);
            }
        }
#pragma unroll
        for (int r=0;r<8;r++){
            const int i = i0+r;
            if (i >= HW) break;
            float s[8];
#pragma unroll
            for (int g=0;g<4;g++){
                upk2(acc[r][g], s[2*g], s[2*g+1]);
                int c0 = 2*lane + 64*g;
                if (c0 >= HW) { s[2*g]=-1e30f; s[2*g+1]=-1e30f; }
            }
            float mx = s[0];
#pragma unroll
            for (int k=1;k<8;k++) mx = fmaxf(mx, s[k]);
#pragma unroll
            for (int o=16;o>0;o>>=1) mx = fmaxf(mx, __shfl_xor_sync(0xffffffffu, mx, o));
            float se=0.f, pv=0.f;
#pragma unroll
            for (int g=0;g<4;g++){
                int c0 = 2*lane + 64*g;
                float e0 = __expf(s[2*g]  -mx);
                float e1 = __expf(s[2*g+1]-mx);
                se += e0+e1;
                pv += e0*vs[c0] + e1*vs[c0+1];
            }
#pragma unroll
            for (int o=16;o>0;o>>=1){
                se += __shfl_xor_sync(0xffffffffu,se,o);
                pv += __shfl_xor_sync(0xffffffffu,pv,o);
            }
            if (lane==0) g_m[n*HW+i] = 1.f/(1.f+__expf(-(pv/se)));
        }
    }
}

// ---------------------------------------------------------------------------
// Kernel 3: 32x upsample + [1-m, m]. Each block does TWO 32-row bands with
// double-buffered smem: band A drains via TMA while band B is being built.
// grid (7, 256): blockIdx.x = band pair, blockIdx.y = n*2+ch.
// ---------------------------------------------------------------------------
__global__ __launch_bounds__(448) void k_mask(float* __restrict__ out)
{
    __shared__ __align__(16) float buf[2][8*OUTW];  // 2 x 14336 B
    __shared__ float rv[28];
    const int cr0 = blockIdx.x*2;                   // bands cr0, cr0+1
    const int nc  = blockIdx.y;
    const int n   = nc>>1, ch = nc&1;
    const int t   = threadIdx.x;                    // 0..447

    if (t < 28){
        int band = t / 14, cell = t % 14;
        float m = g_m[n*HW + (cr0+band)*14 + cell];
        rv[t] = ch ? m : 1.f - m;
    }
    __syncthreads();

    unsigned sm0, sm1;
    asm("{ .reg .u64 tt; cvta.to.shared.u64 tt, %1; cvt.u32.u64 %0, tt; }" : "=r"(sm0) : "l"(&buf[0][0]));
    asm("{ .reg .u64 tt; cvta.to.shared.u64 tt, %1; cvt.u32.u64 %0, tt; }" : "=r"(sm1) : "l"(&buf[1][0]));
    float* base0 = out + (size_t)nc*OUTW*OUTW + (size_t)cr0*32*OUTW;

    // band 0 build
    {
        float4* b4 = (float4*)buf[0];
#pragma unroll
        for (int u=0; u<2; u++){
            const int idx  = t + 448*u;             // 0..895 float4
            const int col4 = idx % 112;
            const float v  = rv[col4>>3];
            b4[idx] = make_float4(v,v,v,v);
        }
    }
    __syncthreads();
    if (t == 0){
        asm volatile("fence.proxy.async.shared::cta;" ::: "memory");
#pragma unroll
        for (int rep = 0; rep < 4; rep++){
            ull gp = (ull)(base0 + rep*8*OUTW);
            asm volatile("cp.async.bulk.global.shared::cta.bulk_group [%0], [%1], %2;"
                         :: "l"(gp), "r"(sm0), "r"(8*OUTW*4) : "memory");
        }
        asm volatile("cp.async.bulk.commit_group;" ::: "memory");
    }

    // band 1 build (overlaps band 0 drain)
    {
        float4* b4 = (float4*)buf[1];
#pragma unroll
        for (int u=0; u<2; u++){
            const int idx  = t + 448*u;
            const int col4 = idx % 112;
            const float v  = rv[14 + (col4>>3)];
            b4[idx] = make_float4(v,v,v,v);
        }
    }
    __syncthreads();
    if (t == 0){
        asm volatile("fence.proxy.async.shared::cta;" ::: "memory");
        float* base1 = base0 + 32*OUTW;
#pragma unroll
        for (int rep = 0; rep < 4; rep++){
            ull gp = (ull)(base1 + rep*8*OUTW);
            asm volatile("cp.async.bulk.global.shared::cta.bulk_group [%0], [%1], %2;"
                         :: "l"(gp), "r"(sm1), "r"(8*OUTW*4) : "memory");
        }
        asm volatile("cp.async.bulk.commit_group;" ::: "memory");
        asm volatile("cp.async.bulk.wait_group 0;" ::: "memory");
    }
}

// ---------------------------------------------------------------------------
extern "C" void kernel_launch(void* const* d_in, const int* in_sizes, int n_in,
                              void* d_out, int out_size)
{
    const float* x     = (const float*)d_in[0];
    const float* lam   = (const float*)d_in[1];
    const int*   index = (const int*)  d_in[2];
    const float* Wq    = (const float*)d_in[3];
    const float* bq    = (const float*)d_in[4];
    const float* Wv    = (const float*)d_in[5];
    const float* bv    = (const float*)d_in[6];

    float* out   = (float*)d_out;
    float* vtail = out + MASK_ELEMS;

    const int smem1 = CH*32*(int)sizeof(float);                        // 32,768 B
    const int smem2 = (ICN*YW + ICN*256 + 256) * (int)sizeof(float);   // 123,904 B
    cudaFuncSetAttribute(k_linear, cudaFuncAttributeMaxDynamicSharedMemorySize, smem1);
    cudaFuncSetAttribute(k_attn,   cudaFuncAttributeMaxDynamicSharedMemorySize, smem2);

    k_value <<<NT, 196>>>(x, Wq, Wv, bv, lam, index, vtail);
    k_linear<<<dim3(2, NT), 224, smem1>>>(x);
    k_attn  <<<NT, 512, smem2>>>(Wq, bq, lam, index);
    k_mask  <<<dim3(7, 256), 448>>>(out);
}